// round 5
// baseline (speedup 1.0000x reference)
#include <cuda_runtime.h>
#include <math.h>

#define RING 256
#define DD   128
#define SD   42
#define G3   126
#define BB   512
#define TT   512
#define NCLS 1000
#define INPD 64
#define PBB  8        // batches per CTA in phase B

// static device scratch (no runtime allocation)
__device__ float g_gx[(size_t)BB * TT * G3];     // 132 MB gate inputs
__device__ float g_u [(size_t)BB * TT * DD];     // 134 MB write vectors
__device__ float g_jg[(size_t)BB * TT * 8];      // 8.4 MB per-warp ju/gu partials
__device__ float g_wct[INPD * 128];
__device__ float g_cc[128];
__device__ int   g_hidx[(size_t)BB * TT];        // hit list (t indices)
__device__ float g_hcoef[(size_t)BB * TT];       // hit coefficients
__device__ int   g_hcnt[BB];

// ---------------- packed f32x2 helpers ----------------
__device__ __forceinline__ unsigned long long pack2(float a, float b) {
    unsigned long long r; asm("mov.b64 %0,{%1,%2};" : "=l"(r) : "f"(a), "f"(b)); return r;
}
__device__ __forceinline__ void fma2(unsigned long long& acc, unsigned long long a, unsigned long long b) {
    asm("fma.rn.f32x2 %0,%1,%2,%0;" : "+l"(acc) : "l"(a), "l"(b));
}
__device__ __forceinline__ float unpack_sum(unsigned long long a) {
    float lo, hi; asm("mov.b64 {%0,%1},%2;" : "=f"(lo), "=f"(hi) : "l"(a)); return lo + hi;
}

// accurate-ish math (R1 recipe: rel_err 9.4e-7)
__device__ __forceinline__ float sigm(float x) { return 1.0f / (1.0f + __expf(-x)); }

// exact 5-tap Gaussian softmax window (R1 recipe)
__device__ __forceinline__ void ringkern(float p, int* pos, float* wn) {
    float base = floorf(p);
    float frac = p - base;
    int ib = (int)base;
    float e[5]; float s = 0.f;
#pragma unroll
    for (int k = 0; k < 5; k++) {
        pos[k] = (ib + k - 2 + RING) & (RING - 1);
        float d = (float)(k - 2) - frac;
        e[k] = __expf(d * d * (-0.125f));
        s += e[k];
    }
    float inv = 1.0f / s;
#pragma unroll
    for (int k = 0; k < 5; k++) wn[k] = e[k] * inv;
}

// 42-dim dot: packed weights (21 x f32x2) vs h_s (smem broadcast), 2 chains
__device__ __forceinline__ float dot42(const unsigned long long* w, const float* h_s) {
    const ulonglong2* hp = (const ulonglong2*)h_s;
    unsigned long long a0 = 0ull, a1 = 0ull;
#pragma unroll
    for (int q = 0; q < 10; q++) {
        ulonglong2 hh = hp[q];
        fma2(a0, w[2 * q], hh.x);
        fma2(a1, w[2 * q + 1], hh.y);
    }
    fma2(a0, w[20], ((const unsigned long long*)h_s)[20]);
    return unpack_sum(a0) + unpack_sum(a1);
}

// ---------------------------------------------------------------------------
// Kernel 0: fuse w_ih@w_proj -> g_wct, g_cc
// ---------------------------------------------------------------------------
__global__ void prep_kernel(const float* __restrict__ w_ih, const float* __restrict__ w_proj,
                            const float* __restrict__ b_ih, const float* __restrict__ b_proj) {
    int tid = blockIdx.x * blockDim.x + threadIdx.x;
    int nt  = gridDim.x * blockDim.x;
    for (int idx = tid; idx < INPD * 128; idx += nt) {
        int i = idx >> 7, j = idx & 127;
        float acc = 0.f;
        if (j < G3)
            for (int k = 0; k < SD; k++)
                acc = fmaf(w_ih[j * SD + k], w_proj[k * INPD + i], acc);
        g_wct[idx] = acc;
    }
    for (int j = tid; j < 128; j += nt) {
        float acc = 0.f;
        if (j < G3) {
            acc = b_ih[j];
            for (int k = 0; k < SD; k++) acc = fmaf(w_ih[j * SD + k], b_proj[k], acc);
        }
        g_cc[j] = acc;
    }
}

// ---------------------------------------------------------------------------
// Kernel 1: gx = x @ Wct + cc  (32 rows/block, 40.7 KB smem)
// ---------------------------------------------------------------------------
__global__ __launch_bounds__(256, 2) void gx_kernel(const float* __restrict__ x) {
    __shared__ float xs[32 * INPD];
    __shared__ __align__(16) float wcs[INPD * 128];
    __shared__ float ccs[128];
    int tid = threadIdx.x;
    size_t row0 = (size_t)blockIdx.x * 32;

    for (int i = tid; i < 32 * INPD; i += 256) xs[i] = x[row0 * INPD + i];
    for (int i = tid; i < INPD * 128; i += 256) wcs[i] = g_wct[i];
    if (tid < 128) ccs[tid] = g_cc[tid];
    __syncthreads();

    int r  = tid >> 3;
    int jg = (tid & 7) << 4;

    unsigned long long acc[8];
#pragma unroll
    for (int q = 0; q < 8; q++)
        acc[q] = pack2(ccs[jg + 2 * q], ccs[jg + 2 * q + 1]);

#pragma unroll 8
    for (int i = 0; i < INPD; i++) {
        float xv = xs[r * INPD + i];
        unsigned long long xp = pack2(xv, xv);
        const ulonglong2* wr = (const ulonglong2*)&wcs[i * 128 + jg];
#pragma unroll
        for (int q2 = 0; q2 < 4; q2++) {
            ulonglong2 w2 = wr[q2];
            fma2(acc[2 * q2],     xp, w2.x);
            fma2(acc[2 * q2 + 1], xp, w2.y);
        }
    }
    float* o0 = &g_gx[(row0 + r) * (size_t)G3];
#pragma unroll
    for (int q = 0; q < 8; q++) {
        float lo, hi;
        asm("mov.b64 {%0,%1},%2;" : "=f"(lo), "=f"(hi) : "l"(acc[q]));
        int j = jg + 2 * q;
        if (j < G3)     o0[j]     = lo;
        if (j + 1 < G3) o0[j + 1] = hi;
    }
}

// ---------------------------------------------------------------------------
// Kernel 2 (phase A): h/u recurrence only. 1 CTA/batch, 128 threads.
//   iteration i: R-phase (gh_i from h_i; u_{i-1} from h_i) | B1 |
//                W-phase (GRU -> h_{i+1}; gx prefetch i+2)  | B2
// ---------------------------------------------------------------------------
__global__ __launch_bounds__(128, 4) void phaseA_kernel(
    const float* __restrict__ w_hh, const float* __restrict__ b_hh,
    const float* __restrict__ w_bridge, const float* __restrict__ b_bridge,
    const float* __restrict__ w_jump, const float* __restrict__ w_gate)
{
    __shared__ __align__(16) float h_s[44];
    __shared__ float gh_s[128];

    const int tid  = threadIdx.x;
    const int lane = tid & 31;
    const int wid  = tid >> 5;
    const int b    = blockIdx.x;

    if (tid < 44) h_s[tid] = 0.f;

    unsigned long long whh_r[21], wbr_r[21];
    if (tid < G3) {
#pragma unroll
        for (int q = 0; q < 21; q++)
            whh_r[q] = pack2(w_hh[tid * SD + 2 * q], w_hh[tid * SD + 2 * q + 1]);
    } else {
#pragma unroll
        for (int q = 0; q < 21; q++) whh_r[q] = 0ull;
    }
#pragma unroll
    for (int q = 0; q < 21; q++)
        wbr_r[q] = pack2(w_bridge[tid * SD + 2 * q], w_bridge[tid * SD + 2 * q + 1]);

    const float bhh = (tid < G3) ? b_hh[tid] : 0.f;
    const float bbr = b_bridge[tid];
    const float wj  = w_jump[tid];
    const float wg  = w_gate[tid];

    const float* gx = g_gx + (size_t)b * TT * G3;
    float*       up = g_u  + (size_t)b * TT * DD;
    float*       jg = g_jg + (size_t)b * TT * 8;

    // double-buffered gx prefetch (2 steps ahead)
    float a0 = 0.f, a1 = 0.f, a2 = 0.f, c0 = 0.f, c1 = 0.f, c2 = 0.f;
    if (tid < SD) {
        a0 = __ldcs(gx + tid);          a1 = __ldcs(gx + SD + tid);          a2 = __ldcs(gx + 2 * SD + tid);
        c0 = __ldcs(gx + G3 + tid);     c1 = __ldcs(gx + G3 + SD + tid);     c2 = __ldcs(gx + G3 + 2 * SD + tid);
    }
    __syncthreads();

    for (int i = 0; i <= TT; i++) {
        // ---- R phase: read h_s ----
        if (i < TT && tid < G3) gh_s[tid] = dot42(whh_r, h_s) + bhh;
        if (i > 0) {
            float u = tanhf(dot42(wbr_r, h_s) + bbr);
            __stcs(up + (size_t)(i - 1) * DD + tid, u);
            float jp = wj * u, gp = wg * u;
#pragma unroll
            for (int o = 16; o > 0; o >>= 1) {
                jp += __shfl_xor_sync(0xffffffffu, jp, o);
                gp += __shfl_xor_sync(0xffffffffu, gp, o);
            }
            if (lane == 0) {
                jg[(size_t)(i - 1) * 8 + wid]     = jp;
                jg[(size_t)(i - 1) * 8 + 4 + wid] = gp;
            }
        }
        __syncthreads();                       // B1: gh_s ready; h_s reads done
        // ---- W phase: update h_s ----
        if (i < TT && tid < SD) {
            float rg = sigm(a0 + gh_s[tid]);
            float zg = sigm(a1 + gh_s[SD + tid]);
            float ng = tanhf(a2 + rg * gh_s[2 * SD + tid]);
            h_s[tid] = (1.f - zg) * ng + zg * h_s[tid];
            // rotate buffers, prefetch i+2
            a0 = c0; a1 = c1; a2 = c2;
            int tn = (i + 2 < TT) ? i + 2 : TT - 1;
            const float* gp2 = gx + (size_t)tn * G3;
            c0 = __ldcs(gp2 + tid);
            c1 = __ldcs(gp2 + SD + tid);
            c2 = __ldcs(gp2 + 2 * SD + tid);
        }
        __syncthreads();                       // B2: h_s ready
    }
}

// ---------------------------------------------------------------------------
// Kernel 3 (phase B): pointer scan. 1 thread per batch (8/CTA, 64 CTAs).
//   J/G scalar ring summaries in smem; emits hit list for final read.
// ---------------------------------------------------------------------------
__global__ __launch_bounds__(32, 1) void phaseB_kernel(
    const float* __restrict__ b_jump, const float* __restrict__ b_gate,
    const float* __restrict__ theta)
{
    __shared__ float J_s[PBB][257];
    __shared__ float G_s[PBB][257];
    __shared__ float hist[PBB][TT];

    const int tid = threadIdx.x;
    // cooperative smem zero (J/G only)
    for (int i = tid; i < PBB * 257 * 2; i += 32) {
        ((float*)J_s)[i < PBB * 257 ? i : i] = 0.f;   // contiguous arrays
    }
    // the two arrays are contiguous in smem declaration order; zero both:
    // (above loop covers J_s then G_s since they are laid out sequentially)
    __syncthreads();

    if (tid >= PBB) return;
    const int b = blockIdx.x * PBB + tid;

    float bj = b_jump[0], bg = b_gate[0];
    float ptr = fmodf(theta[0], 256.f);
    if (ptr < 0.f) ptr += 256.f;

    float* J = J_s[tid];
    float* G = G_s[tid];
    float* H = hist[tid];
    const float* jgp = g_jg + (size_t)b * TT * 8;

    for (int t = 0; t < TT; t++) {
        // partials for step t (L2-resident)
        float4 pj = *(const float4*)(jgp + (size_t)t * 8);
        float4 pg = *(const float4*)(jgp + (size_t)t * 8 + 4);
        float ju = (pj.x + pj.y) + (pj.z + pj.w);
        float gu = (pg.x + pg.y) + (pg.z + pg.w);

        // read at old ptr
        int pos[5]; float wn[5];
        ringkern(ptr, pos, wn);
        float jd = bj, gd = bg;
#pragma unroll
        for (int k = 0; k < 5; k++) {
            jd = fmaf(wn[k], J[pos[k]], jd);
            gd = fmaf(wn[k], G[pos[k]], gd);
        }
        float jump = sigm(jd) * 256.f;
        float gate = sigm(gd);
        float dlt = fmodf(jump - ptr + 128.f, 256.f);
        if (dlt < 0.f) dlt += 256.f;
        dlt -= 128.f;
        ptr = fmodf(ptr + gate * dlt, 256.f);
        if (ptr < 0.f) ptr += 256.f;
        H[t] = ptr;

        // write at new ptr
        int pos2[5]; float wn2[5];
        ringkern(ptr, pos2, wn2);
#pragma unroll
        for (int k = 0; k < 5; k++) {
            J[pos2[k]] += wn2[k] * ju;
            G[pos2[k]] += wn2[k] * gu;
        }
    }

    // build hit list for final soft read
    float pF = H[TT - 1];
    int posf[5]; float wnf[5];
    ringkern(pF, posf, wnf);
    int ib_f = (int)floorf(pF);
    int cnt = 0;
    int*   hix = g_hidx  + (size_t)b * TT;
    float* hcf = g_hcoef + (size_t)b * TT;
    for (int t = 0; t < TT; t++) {
        float pt = H[t];
        int ib_t = (int)floorf(pt);
        int dw = ((ib_t - ib_f + 128) & 255) - 128;
        if (dw > -5 && dw < 5) {
            int pd[5]; float wn2[5];
            ringkern(pt, pd, wn2);
            float coef = 0.f;
#pragma unroll
            for (int k = 0; k < 5; k++) {
                int m = k + dw;
                if (m >= 0 && m < 5) coef = fmaf(wnf[m], wn2[k], coef);
            }
            hix[cnt] = t;
            hcf[cnt] = coef;
            cnt++;
        }
    }
    g_hcnt[b] = cnt;
}

// ---------------------------------------------------------------------------
// Kernel 4: final read + classifier. 1 CTA/batch.
// ---------------------------------------------------------------------------
__global__ __launch_bounds__(128) void final_kernel(
    const float* __restrict__ w_cls, const float* __restrict__ b_cls,
    float* __restrict__ out)
{
    __shared__ int   idx_s[TT];
    __shared__ float cf_s[TT];
    __shared__ float r_s[128];

    const int tid = threadIdx.x;
    const int b   = blockIdx.x;

    int cnt = g_hcnt[b];
    for (int i = tid; i < cnt; i += 128) {
        idx_s[i] = g_hidx[(size_t)b * TT + i];
        cf_s[i]  = g_hcoef[(size_t)b * TT + i];
    }
    __syncthreads();

    const float* up = g_u + (size_t)b * TT * DD;
    float rf = 0.f;
    for (int i = 0; i < cnt; i++)
        rf = fmaf(cf_s[i], __ldcg(up + (size_t)idx_s[i] * DD + tid), rf);
    r_s[tid] = rf;
    __syncthreads();

    for (int n = tid; n < NCLS; n += 128) {
        float acc = b_cls[n];
        const float4* wr = (const float4*)(w_cls + (size_t)n * DD);
#pragma unroll 8
        for (int q = 0; q < 32; q++) {
            float4 w4 = wr[q];
            acc = fmaf(r_s[q * 4 + 0], w4.x, acc);
            acc = fmaf(r_s[q * 4 + 1], w4.y, acc);
            acc = fmaf(r_s[q * 4 + 2], w4.z, acc);
            acc = fmaf(r_s[q * 4 + 3], w4.w, acc);
        }
        out[(size_t)b * NCLS + n] = acc;
    }
}

// ---------------------------------------------------------------------------
extern "C" void kernel_launch(void* const* d_in, const int* in_sizes, int n_in,
                              void* d_out, int out_size) {
    const float* x        = (const float*)d_in[0];
    const float* theta    = (const float*)d_in[1];
    const float* w_proj   = (const float*)d_in[2];
    const float* b_proj   = (const float*)d_in[3];
    const float* w_ih     = (const float*)d_in[4];
    const float* w_hh     = (const float*)d_in[5];
    const float* b_ih     = (const float*)d_in[6];
    const float* b_hh     = (const float*)d_in[7];
    const float* w_bridge = (const float*)d_in[8];
    const float* b_bridge = (const float*)d_in[9];
    const float* w_jump   = (const float*)d_in[10];
    const float* b_jump   = (const float*)d_in[11];
    const float* w_gate   = (const float*)d_in[12];
    const float* b_gate   = (const float*)d_in[13];
    const float* w_cls    = (const float*)d_in[14];
    const float* b_cls    = (const float*)d_in[15];
    float* out = (float*)d_out;

    prep_kernel<<<16, 256>>>(w_ih, w_proj, b_ih, b_proj);
    gx_kernel<<<(BB * TT) / 32, 256>>>(x);
    phaseA_kernel<<<BB, 128>>>(w_hh, b_hh, w_bridge, b_bridge, w_jump, w_gate);
    phaseB_kernel<<<BB / PBB, 32>>>(b_jump, b_gate, theta);
    final_kernel<<<BB, 128>>>(w_cls, b_cls, out);
}